// round 4
// baseline (speedup 1.0000x reference)
#include <cuda_runtime.h>
#include <cuda_bf16.h>

// Grouped rational activation:
//   out = P(z) / Q(z),  P degree 5 (6 coeffs, shared across groups),
//   Q(z) = 1 + |b1| z + |b2| z^2 + |b3| z^3 + |b4| z^4  (per-group b's)
// Shapes: x (4, 4096, 2048) fp32, G=8 groups, Dpg=256.
// DRAM-bound pointwise. 4x float4 per thread, stride n4/4 (all four elements
// share one group since n4/4 is a multiple of 512 = float4s per D-row).
// All 4 data loads front-batched for MLP=4.

#define D_TOTAL     2048
#define GROUPS      8

__global__ __launch_bounds__(256)
void kat_group_kernel(const float4* __restrict__ x,
                      const float4* __restrict__ wnum4,  // 6 floats: float4 + float2
                      const float4* __restrict__ wden4,  // (8,4) -> 8 float4 rows
                      float4* __restrict__ out,
                      int n4q)                            // n4 / 4
{
    int i = blockIdx.x * blockDim.x + threadIdx.x;
    if (i >= n4q) return;

    // group of this float4 (identical for all 4 strided elements:
    // n4q % 512 == 0, and (i & 511) / 64 selects the group)
    int g = (i >> 6) & (GROUPS - 1);

    // front-batch the four data loads (MLP_p1 = 4)
    float4 v0 = x[i];
    float4 v1 = x[i +     n4q];
    float4 v2 = x[i + 2 * n4q];
    float4 v3 = x[i + 3 * n4q];

    // numerator coeffs: one float4 + one float2 (L1-resident)
    float4 aa = __ldg(wnum4);
    float2 ab = __ldg((const float2*)(wnum4) + 2);
    float a0 = aa.x, a1 = aa.y, a2 = aa.z, a3 = aa.w, a4 = ab.x, a5 = ab.y;

    // denominator coeffs for this group: c0=1, c1..c4 = |b1..b4|
    float4 bb = __ldg(wden4 + g);
    float c1 = fabsf(bb.x), c2 = fabsf(bb.y), c3 = fabsf(bb.z), c4 = fabsf(bb.w);

    float zs[16] = {v0.x, v0.y, v0.z, v0.w,
                    v1.x, v1.y, v1.z, v1.w,
                    v2.x, v2.y, v2.z, v2.w,
                    v3.x, v3.y, v3.z, v3.w};
    float os[16];

    #pragma unroll
    for (int k = 0; k < 16; ++k) {
        float z = zs[k];

        // numerator Horner, degree 5
        float p = fmaf(a5, z, a4);
        p = fmaf(p, z, a3);
        p = fmaf(p, z, a2);
        p = fmaf(p, z, a1);
        p = fmaf(p, z, a0);

        // denominator Horner, degree 4, c0 = 1
        float q = fmaf(c4, z, c3);
        q = fmaf(q, z, c2);
        q = fmaf(q, z, c1);
        q = fmaf(q, z, 1.0f);

        os[k] = __fdividef(p, q);
    }

    out[i]           = make_float4(os[0],  os[1],  os[2],  os[3]);
    out[i +     n4q] = make_float4(os[4],  os[5],  os[6],  os[7]);
    out[i + 2 * n4q] = make_float4(os[8],  os[9],  os[10], os[11]);
    out[i + 3 * n4q] = make_float4(os[12], os[13], os[14], os[15]);
}

extern "C" void kernel_launch(void* const* d_in, const int* in_sizes, int n_in,
                              void* d_out, int out_size)
{
    const float* x    = (const float*)d_in[0];
    const float* wnum = (const float*)d_in[1];
    const float* wden = (const float*)d_in[2];
    // d_in[3] = num_groups (int32 on device) — fixed at 8 for this problem

    int n   = in_sizes[0];   // 33_554_432 floats
    int n4q = n / 16;        // 2_097_152 (quads of float4)

    int threads = 256;
    int blocks  = (n4q + threads - 1) / threads;

    kat_group_kernel<<<blocks, threads>>>(
        (const float4*)x, (const float4*)wnum, (const float4*)wden,
        (float4*)d_out, n4q);
}